// round 11
// baseline (speedup 1.0000x reference)
#include <cuda_runtime.h>
#include <cuda_fp16.h>
#include <cuda_bf16.h>
#include <cstdint>
#include <float.h>

// ---------------------------------------------------------------------------
#define N 8192
#define D 1024
#define BM 128
#define BN 128
#define BK 64                 // bf16 elems per chunk (128 B/row)
#define NJT (N / BN)          // 64 j-tiles
#define EPS 20.0f             // candidate margin (worst-case bf16+fp16 err ~13.2)
#define STAGES 3
#define MAXC 256              // candidate buffer per row

// __device__ globals (allocation-free rule)
__device__ float          g_n2[N];
__device__ __nv_bfloat16  g_Ah[(size_t)N * D];   // 16 MB
__device__ __nv_bfloat16  g_Bh[(size_t)N * D];   // 16 MB
__device__ __half         g_S[(size_t)N * N];    // approx scores (128 MB)
__device__ float          g_tmax[(size_t)N * NJT];
__device__ float          g_rowmax[N];

// ---------------------------------------------------------------------------
__device__ __forceinline__ uint32_t smem_u32(const void* p) {
    uint32_t a;
    asm("{ .reg .u64 t; cvta.to.shared.u64 t, %1; cvt.u32.u64 %0, t; }" : "=r"(a) : "l"(p));
    return a;
}
__device__ __forceinline__ void cp_async16(uint32_t saddr, const void* gaddr) {
    asm volatile("cp.async.cg.shared.global [%0], [%1], 16;" :: "r"(saddr), "l"(gaddr));
}
#define CP_COMMIT()  asm volatile("cp.async.commit_group;" ::: "memory")
#define CP_WAIT(nn)  asm volatile("cp.async.wait_group %0;" :: "n"(nn) : "memory")

__device__ __forceinline__ void mma_bf16(float* d, const uint32_t* a, const uint32_t* b) {
    asm volatile(
        "mma.sync.aligned.m16n8k16.row.col.f32.bf16.bf16.f32 "
        "{%0,%1,%2,%3}, {%4,%5,%6,%7}, {%8,%9}, {%0,%1,%2,%3};"
        : "+f"(d[0]), "+f"(d[1]), "+f"(d[2]), "+f"(d[3])
        : "r"(a[0]), "r"(a[1]), "r"(a[2]), "r"(a[3]), "r"(b[0]), "r"(b[1]));
}
__device__ __forceinline__ void ldsm_x4(uint32_t* r, uint32_t addr) {
    asm volatile("ldmatrix.sync.aligned.m8n8.x4.shared.b16 {%0,%1,%2,%3}, [%4];"
        : "=r"(r[0]), "=r"(r[1]), "=r"(r[2]), "=r"(r[3]) : "r"(addr));
}

// ---------------------------------------------------------------------------
// Fused conversion: blocks [0, N/8) convert B rows + compute n2;
// blocks [N/8, 2N/8) convert A rows. One warp per row.
__global__ void cvt_all_kernel(const float* __restrict__ A, const float* __restrict__ B,
                               __nv_bfloat16* __restrict__ Ah, __nv_bfloat16* __restrict__ Bh) {
    const int bid  = blockIdx.x;
    const int wrow = threadIdx.x >> 5;
    const int lane = threadIdx.x & 31;
    if (bid < N / 8) {
        int row = bid * 8 + wrow;
        const float4* p = reinterpret_cast<const float4*>(B + (size_t)row * D);
        uint2* q = reinterpret_cast<uint2*>(Bh + (size_t)row * D);
        float s = 0.f;
#pragma unroll
        for (int it = 0; it < (D / 4) / 32; ++it) {
            float4 v = p[it * 32 + lane];
            s += v.x * v.x + v.y * v.y + v.z * v.z + v.w * v.w;
            __nv_bfloat162 lo = __floats2bfloat162_rn(v.x, v.y);
            __nv_bfloat162 hi = __floats2bfloat162_rn(v.z, v.w);
            q[it * 32 + lane] = make_uint2(*reinterpret_cast<uint32_t*>(&lo),
                                           *reinterpret_cast<uint32_t*>(&hi));
        }
#pragma unroll
        for (int off = 16; off > 0; off >>= 1) s += __shfl_xor_sync(0xFFFFFFFFu, s, off);
        if (lane == 0) g_n2[row] = s;
    } else {
        int row = (bid - N / 8) * 8 + wrow;
        const float4* p = reinterpret_cast<const float4*>(A + (size_t)row * D);
        uint2* q = reinterpret_cast<uint2*>(Ah + (size_t)row * D);
#pragma unroll
        for (int it = 0; it < (D / 4) / 32; ++it) {
            float4 v = p[it * 32 + lane];
            __nv_bfloat162 lo = __floats2bfloat162_rn(v.x, v.y);
            __nv_bfloat162 hi = __floats2bfloat162_rn(v.z, v.w);
            q[it * 32 + lane] = make_uint2(*reinterpret_cast<uint32_t*>(&lo),
                                           *reinterpret_cast<uint32_t*>(&hi));
        }
    }
}

// ---------------------------------------------------------------------------
// Phase 1 (R7 shape): bf16 mma.sync GEMM (128x128, K=1024), BK=64, 3-stage
// cp.async, XOR-swizzled smem (128 B rows), ldmatrix fragments.
// score = n2[j] - 2*dot -> fp16 g_S + per-(row,tile) fp32 max.
// ---------------------------------------------------------------------------
#define STG_BYTES (128 * 128)                 // 16384 per matrix per stage
#define SM_B_OFF  (STAGES * STG_BYTES)        // 49152
#define SM_N2_OFF (2 * STAGES * STG_BYTES)    // 98304
#define SM_TM_OFF (SM_N2_OFF + 512)
#define SM_TOTAL  (SM_TM_OFF + 2048)          // 100864

__global__ void __launch_bounds__(256, 2)
gemm_kernel() {
    extern __shared__ __align__(16) char sm[];
    const uint32_t sb = smem_u32(sm);
    const int tid  = threadIdx.x;
    const int lane = tid & 31;
    const int wid  = tid >> 5;
    const int wm   = wid >> 2;       // 0..1
    const int wn   = wid & 3;        // 0..3
    const int g    = lane >> 2;      // 0..7
    const int tig  = lane & 3;       // 0..3

    const int it = blockIdx.x, jt = blockIdx.y;
    const int i0 = it * BM, j0 = jt * BN;

    float* n2s   = reinterpret_cast<float*>(sm + SM_N2_OFF);
    float* tmaxs = reinterpret_cast<float*>(sm + SM_TM_OFF);
    if (tid < BN) n2s[tid] = g_n2[j0 + tid];

    // gmem->smem loader: 8 threads per 128-B row, 4 row-waves per matrix
    const int lr   = tid >> 3;             // 0..31
    const int lc16 = tid & 7;              // 16B-chunk col 0..7

    const __nv_bfloat16* Ag = g_Ah + (size_t)i0 * D;
    const __nv_bfloat16* Bg = g_Bh + (size_t)j0 * D;

    auto issue = [&](int c) {
        const int st = ((unsigned)c) % STAGES;
        uint32_t sa  = sb + st * STG_BYTES;
        uint32_t sbb = sb + SM_B_OFF + st * STG_BYTES;
        const char* ag = reinterpret_cast<const char*>(Ag + c * BK);
        const char* bg = reinterpret_cast<const char*>(Bg + c * BK);
#pragma unroll
        for (int v = 0; v < 4; ++v) {
            int r = lr + v * 32;
            uint32_t soff = (uint32_t)(r * 128 + ((lc16 ^ (r & 7)) * 16));
            cp_async16(sa  + soff, ag + (size_t)r * (D * 2) + lc16 * 16);
            cp_async16(sbb + soff, bg + (size_t)r * (D * 2) + lc16 * 16);
        }
        CP_COMMIT();
    };

    issue(0);
    issue(1);

    // ldmatrix per-lane constants (q = lane>>3 selects the 8x8 sub-matrix)
    const int q  = lane >> 3;
    const int r8 = lane & 7;
    const uint32_t arow = (uint32_t)(((q & 1) * 8 + r8) * 128);
    const int acol = q >> 1;                 // 0/1 (16B units)
    const uint32_t brow = (uint32_t)(((q >> 1) * 8 + r8) * 128);
    const int bcol = q & 1;

    float acc[4][4][4];
#pragma unroll
    for (int m = 0; m < 4; ++m)
#pragma unroll
        for (int n = 0; n < 4; ++n)
#pragma unroll
            for (int qq = 0; qq < 4; ++qq) acc[m][n][qq] = 0.f;

    const int NCH = D / BK;   // 16
    for (int c = 0; c < NCH; ++c) {
        const int st = ((unsigned)c) % STAGES;
        if (c == NCH - 1) CP_WAIT(0); else CP_WAIT(1);
        __syncthreads();
        if (c + 2 < NCH) issue(c + 2);   // lands 2 compute-blocks ahead

        const uint32_t sA = sb + st * STG_BYTES + (uint32_t)((wm * 64) * 128);
        const uint32_t sB = sb + SM_B_OFF + st * STG_BYTES + (uint32_t)((wn * 32) * 128);
#pragma unroll
        for (int ks = 0; ks < BK / 16; ++ks) {      // 4 independent k-slices
            uint32_t a[4][4], b[4][2];
#pragma unroll
            for (int mt = 0; mt < 4; ++mt)
                ldsm_x4(a[mt], sA + (uint32_t)(mt * 16 * 128) + arow
                               + (uint32_t)((((ks * 2 + acol) ^ r8) & 7) * 16));
#pragma unroll
            for (int p = 0; p < 2; ++p) {
                uint32_t bp[4];
                ldsm_x4(bp, sB + (uint32_t)(p * 16 * 128) + brow
                            + (uint32_t)((((ks * 2 + bcol) ^ r8) & 7) * 16));
                b[2 * p][0]     = bp[0];
                b[2 * p][1]     = bp[1];
                b[2 * p + 1][0] = bp[2];
                b[2 * p + 1][1] = bp[3];
            }
#pragma unroll
            for (int mt = 0; mt < 4; ++mt)
#pragma unroll
                for (int nt = 0; nt < 4; ++nt)
                    mma_bf16(acc[mt][nt], a[mt], b[nt]);
        }
    }

    // Epilogue: scores, fp16 store, per-row max
    __syncthreads();
    float rmax[8];
#pragma unroll
    for (int qq = 0; qq < 8; ++qq) rmax[qq] = -FLT_MAX;

#pragma unroll
    for (int mt = 0; mt < 4; ++mt) {
        const int r0 = wm * 64 + mt * 16 + g;
        const int r1 = r0 + 8;
#pragma unroll
        for (int nt = 0; nt < 4; ++nt) {
            const int c0 = wn * 32 + nt * 8 + tig * 2;
            float s00 = n2s[c0]     - 2.f * acc[mt][nt][0];
            float s01 = n2s[c0 + 1] - 2.f * acc[mt][nt][1];
            float s10 = n2s[c0]     - 2.f * acc[mt][nt][2];
            float s11 = n2s[c0 + 1] - 2.f * acc[mt][nt][3];
            *reinterpret_cast<__half2*>(&g_S[(size_t)(i0 + r0) * N + j0 + c0]) =
                __floats2half2_rn(s00, s01);
            *reinterpret_cast<__half2*>(&g_S[(size_t)(i0 + r1) * N + j0 + c0]) =
                __floats2half2_rn(s10, s11);
            rmax[mt * 2]     = fmaxf(rmax[mt * 2],     fmaxf(s00, s01));
            rmax[mt * 2 + 1] = fmaxf(rmax[mt * 2 + 1], fmaxf(s10, s11));
        }
    }
#pragma unroll
    for (int qq = 0; qq < 8; ++qq) {
        rmax[qq] = fmaxf(rmax[qq], __shfl_xor_sync(0xFFFFFFFFu, rmax[qq], 1));
        rmax[qq] = fmaxf(rmax[qq], __shfl_xor_sync(0xFFFFFFFFu, rmax[qq], 2));
    }
    if (tig == 0) {
#pragma unroll
        for (int mt = 0; mt < 4; ++mt) {
            tmaxs[(wm * 64 + mt * 16 + g) * 4 + wn]     = rmax[mt * 2];
            tmaxs[(wm * 64 + mt * 16 + g + 8) * 4 + wn] = rmax[mt * 2 + 1];
        }
    }
    __syncthreads();
    if (tid < BM) {
        float m = fmaxf(fmaxf(tmaxs[tid * 4 + 0], tmaxs[tid * 4 + 1]),
                        fmaxf(tmaxs[tid * 4 + 2], tmaxs[tid * 4 + 3]));
        g_tmax[(size_t)(i0 + tid) * NJT + jt] = m;
    }
}

// ---------------------------------------------------------------------------
__global__ void rowmax_kernel() {
    int row  = blockIdx.x * 8 + (threadIdx.x >> 5);
    int lane = threadIdx.x & 31;
    float m = fmaxf(g_tmax[(size_t)row * NJT + lane],
                    g_tmax[(size_t)row * NJT + 32 + lane]);
#pragma unroll
    for (int off = 16; off > 0; off >>= 1)
        m = fmaxf(m, __shfl_xor_sync(0xFFFFFFFFu, m, off));
    if (lane == 0) g_rowmax[row] = m;
}

// ---------------------------------------------------------------------------
// Phase 3: vectorized full scan + WARP-PARALLEL exact rescore + gather.
// One CTA per row; candidate c rescored by warp c%8 (no serial block barriers).
// ---------------------------------------------------------------------------
__global__ void __launch_bounds__(256)
select_kernel(const float* __restrict__ A, const float* __restrict__ B,
              float* __restrict__ out) {
    const int i = blockIdx.x;
    const int tid = threadIdx.x, lane = tid & 31, wid = tid >> 5;

    __shared__ int   cnt;
    __shared__ int   cand[MAXC];
    __shared__ float wval[8];
    __shared__ int   widx[8];
    __shared__ int   bestj_s;

    const float thresh = g_rowmax[i] - EPS;
    const __half hth = __float2half_rn(thresh);

    // full A row in registers, warp-replicated: lane holds elems [lane*4 + k*128)
    float4 areg[8];
    const float4* Arow = reinterpret_cast<const float4*>(A + (size_t)i * D);
#pragma unroll
    for (int k = 0; k < 8; ++k) areg[k] = Arow[lane + k * 32];

    if (tid == 0) cnt = 0;
    __syncthreads();

    // vectorized scan (4 independent uint4 loads per thread)
    const uint4* srow4 = reinterpret_cast<const uint4*>(g_S + (size_t)i * N);
    for (int base = tid; base < N / 8; base += 256) {
        uint4 v = srow4[base];
        uint32_t w[4] = {v.x, v.y, v.z, v.w};
#pragma unroll
        for (int k = 0; k < 4; ++k) {
            __half2 h2 = *reinterpret_cast<__half2*>(&w[k]);
            if (__hgt(__low2half(h2), hth)) {
                int p = atomicAdd(&cnt, 1);
                if (p < MAXC) cand[p] = base * 8 + k * 2;
            }
            if (__hgt(__high2half(h2), hth)) {
                int p = atomicAdd(&cnt, 1);
                if (p < MAXC) cand[p] = base * 8 + k * 2 + 1;
            }
        }
    }
    __syncthreads();
    const int nc = min(cnt, MAXC);

    // warp-parallel exact rescore
    float bv = -FLT_MAX;
    int   bj = 0x7fffffff;
    for (int c = wid; c < nc; c += 8) {
        const int j = cand[c];
        const float4* brow = reinterpret_cast<const float4*>(B + (size_t)j * D);
        float p = 0.f;
#pragma unroll
        for (int k = 0; k < 8; ++k) {
            float4 b4 = brow[lane + k * 32];
            p += areg[k].x * b4.x + areg[k].y * b4.y
               + areg[k].z * b4.z + areg[k].w * b4.w;
        }
#pragma unroll
        for (int off = 16; off > 0; off >>= 1) p += __shfl_xor_sync(0xFFFFFFFFu, p, off);
        if (lane == 0) {
            float sc = g_n2[j] - 2.f * p;
            if (sc > bv || (sc == bv && j < bj)) { bv = sc; bj = j; }
        }
    }
    if (lane == 0) { wval[wid] = bv; widx[wid] = bj; }
    __syncthreads();
    if (tid == 0) {
        float fv = -FLT_MAX; int fj = 0x7fffffff;
#pragma unroll
        for (int w = 0; w < 8; ++w) {
            float v = wval[w]; int x = widx[w];
            if (v > fv || (v == fv && x < fj)) { fv = v; fj = x; }
        }
        bestj_s = fj;
    }
    __syncthreads();

    const int j = bestj_s;
    reinterpret_cast<float4*>(out + (size_t)i * D)[tid] =
        reinterpret_cast<const float4*>(B + (size_t)j * D)[tid];
}

// ---------------------------------------------------------------------------
extern "C" void kernel_launch(void* const* d_in, const int* in_sizes, int n_in,
                              void* d_out, int out_size) {
    const float* anchor   = (const float*)d_in[0];
    const float* negative = (const float*)d_in[1];
    float* out = (float*)d_out;

    static __nv_bfloat16* s_Ah = nullptr;
    static __nv_bfloat16* s_Bh = nullptr;
    if (!s_Ah) { cudaGetSymbolAddress((void**)&s_Ah, g_Ah);
                 cudaGetSymbolAddress((void**)&s_Bh, g_Bh); }

    cudaFuncSetAttribute(gemm_kernel,
                         cudaFuncAttributeMaxDynamicSharedMemorySize, SM_TOTAL);

    cvt_all_kernel<<<2 * (N / 8), 256>>>(anchor, negative, s_Ah, s_Bh);
    gemm_kernel<<<dim3(N / BM, N / BN), 256, SM_TOTAL>>>();
    rowmax_kernel<<<N / 8, 256>>>();
    select_kernel<<<N, 256>>>(anchor, negative, out);
}

// round 12
// speedup vs baseline: 1.1188x; 1.1188x over previous
#include <cuda_runtime.h>
#include <cuda_fp16.h>
#include <cuda_bf16.h>
#include <cstdint>
#include <float.h>

// ---------------------------------------------------------------------------
#define N 8192
#define D 1024
#define BM 128
#define BN 128
#define BK 64                 // bf16 elems per chunk (128 B/row)
#define NJT (N / BN)          // 64 j-tiles
#define EPS 20.0f             // margin (bf16 dot err bound ~12.2 incl. both sides)
#define STAGES 3
#define MAXC 1024             // per-row candidate capacity (expected ~2-20 used)

// __device__ globals (allocation-free rule)
__device__ float          g_n2[N];
__device__ __nv_bfloat16  g_Ah[(size_t)N * D];   // 16 MB
__device__ __nv_bfloat16  g_Bh[(size_t)N * D];   // 16 MB
__device__ uint32_t       g_rowmaxu[N];          // ordered-uint running rowmax
__device__ int            g_ccnt[N];             // per-row candidate count
__device__ int            g_cand[(size_t)N * MAXC];  // 32 MB

// ---------------------------------------------------------------------------
__device__ __forceinline__ uint32_t smem_u32(const void* p) {
    uint32_t a;
    asm("{ .reg .u64 t; cvta.to.shared.u64 t, %1; cvt.u32.u64 %0, t; }" : "=r"(a) : "l"(p));
    return a;
}
__device__ __forceinline__ void cp_async16(uint32_t saddr, const void* gaddr) {
    asm volatile("cp.async.cg.shared.global [%0], [%1], 16;" :: "r"(saddr), "l"(gaddr));
}
#define CP_COMMIT()  asm volatile("cp.async.commit_group;" ::: "memory")
#define CP_WAIT(nn)  asm volatile("cp.async.wait_group %0;" :: "n"(nn) : "memory")

__device__ __forceinline__ void mma_bf16(float* d, const uint32_t* a, const uint32_t* b) {
    asm volatile(
        "mma.sync.aligned.m16n8k16.row.col.f32.bf16.bf16.f32 "
        "{%0,%1,%2,%3}, {%4,%5,%6,%7}, {%8,%9}, {%0,%1,%2,%3};"
        : "+f"(d[0]), "+f"(d[1]), "+f"(d[2]), "+f"(d[3])
        : "r"(a[0]), "r"(a[1]), "r"(a[2]), "r"(a[3]), "r"(b[0]), "r"(b[1]));
}
__device__ __forceinline__ void ldsm_x4(uint32_t* r, uint32_t addr) {
    asm volatile("ldmatrix.sync.aligned.m8n8.x4.shared.b16 {%0,%1,%2,%3}, [%4];"
        : "=r"(r[0]), "=r"(r[1]), "=r"(r[2]), "=r"(r[3]) : "r"(addr));
}

// ordered-uint encoding: enc monotone in float order; init 0 == -inf-ish
__device__ __forceinline__ uint32_t enc_f(float f) {
    uint32_t u = __float_as_uint(f);
    return (u & 0x80000000u) ? ~u : (u | 0x80000000u);
}
__device__ __forceinline__ float dec_f(uint32_t u) {
    uint32_t v = (u & 0x80000000u) ? (u & 0x7fffffffu) : ~u;
    return __uint_as_float(v);
}

// ---------------------------------------------------------------------------
// Fused conversion + per-launch state reset.
// blocks [0, N/8): convert B rows, compute n2, reset rowmax/ccnt.
// blocks [N/8, 2N/8): convert A rows.
__global__ void cvt_all_kernel(const float* __restrict__ A, const float* __restrict__ B,
                               __nv_bfloat16* __restrict__ Ah, __nv_bfloat16* __restrict__ Bh) {
    const int bid  = blockIdx.x;
    const int wrow = threadIdx.x >> 5;
    const int lane = threadIdx.x & 31;
    if (bid < N / 8) {
        int row = bid * 8 + wrow;
        if (lane == 0) { g_rowmaxu[row] = 0u; g_ccnt[row] = 0; }
        const float4* p = reinterpret_cast<const float4*>(B + (size_t)row * D);
        uint2* q = reinterpret_cast<uint2*>(Bh + (size_t)row * D);
        float s = 0.f;
#pragma unroll
        for (int it = 0; it < (D / 4) / 32; ++it) {
            float4 v = p[it * 32 + lane];
            s += v.x * v.x + v.y * v.y + v.z * v.z + v.w * v.w;
            __nv_bfloat162 lo = __floats2bfloat162_rn(v.x, v.y);
            __nv_bfloat162 hi = __floats2bfloat162_rn(v.z, v.w);
            q[it * 32 + lane] = make_uint2(*reinterpret_cast<uint32_t*>(&lo),
                                           *reinterpret_cast<uint32_t*>(&hi));
        }
#pragma unroll
        for (int off = 16; off > 0; off >>= 1) s += __shfl_xor_sync(0xFFFFFFFFu, s, off);
        if (lane == 0) g_n2[row] = s;
    } else {
        int row = (bid - N / 8) * 8 + wrow;
        const float4* p = reinterpret_cast<const float4*>(A + (size_t)row * D);
        uint2* q = reinterpret_cast<uint2*>(Ah + (size_t)row * D);
#pragma unroll
        for (int it = 0; it < (D / 4) / 32; ++it) {
            float4 v = p[it * 32 + lane];
            __nv_bfloat162 lo = __floats2bfloat162_rn(v.x, v.y);
            __nv_bfloat162 hi = __floats2bfloat162_rn(v.z, v.w);
            q[it * 32 + lane] = make_uint2(*reinterpret_cast<uint32_t*>(&lo),
                                           *reinterpret_cast<uint32_t*>(&hi));
        }
    }
}

// ---------------------------------------------------------------------------
// Phase 1 (R7 mainloop): bf16 mma.sync GEMM (128x128, K=1024), BK=64, 3-stage
// cp.async, XOR-swizzled smem, ldmatrix. Epilogue: NO score matrix — update
// global running rowmax (atomicMax) and append candidates above
// (running_rowmax - EPS) to per-row lists.
// ---------------------------------------------------------------------------
#define STG_BYTES (128 * 128)                 // 16384 per matrix per stage
#define SM_B_OFF  (STAGES * STG_BYTES)        // 49152
#define SM_N2_OFF (2 * STAGES * STG_BYTES)    // 98304
#define SM_TM_OFF (SM_N2_OFF + 512)
#define SM_TH_OFF (SM_TM_OFF + 2048)
#define SM_TOTAL  (SM_TH_OFF + 512)           // 101376

__global__ void __launch_bounds__(256, 2)
gemm_kernel() {
    extern __shared__ __align__(16) char sm[];
    const uint32_t sb = smem_u32(sm);
    const int tid  = threadIdx.x;
    const int lane = tid & 31;
    const int wid  = tid >> 5;
    const int wm   = wid >> 2;       // 0..1
    const int wn   = wid & 3;        // 0..3
    const int g    = lane >> 2;      // 0..7
    const int tig  = lane & 3;       // 0..3

    const int it = blockIdx.x, jt = blockIdx.y;
    const int i0 = it * BM, j0 = jt * BN;

    float* n2s    = reinterpret_cast<float*>(sm + SM_N2_OFF);
    float* tmaxs  = reinterpret_cast<float*>(sm + SM_TM_OFF);
    float* threshs= reinterpret_cast<float*>(sm + SM_TH_OFF);
    if (tid < BN) n2s[tid] = g_n2[j0 + tid];

    // gmem->smem loader: 8 threads per 128-B row, 4 row-waves per matrix
    const int lr   = tid >> 3;             // 0..31
    const int lc16 = tid & 7;              // 16B-chunk col 0..7

    const __nv_bfloat16* Ag = g_Ah + (size_t)i0 * D;
    const __nv_bfloat16* Bg = g_Bh + (size_t)j0 * D;

    auto issue = [&](int c) {
        const int st = ((unsigned)c) % STAGES;
        uint32_t sa  = sb + st * STG_BYTES;
        uint32_t sbb = sb + SM_B_OFF + st * STG_BYTES;
        const char* ag = reinterpret_cast<const char*>(Ag + c * BK);
        const char* bg = reinterpret_cast<const char*>(Bg + c * BK);
#pragma unroll
        for (int v = 0; v < 4; ++v) {
            int r = lr + v * 32;
            uint32_t soff = (uint32_t)(r * 128 + ((lc16 ^ (r & 7)) * 16));
            cp_async16(sa  + soff, ag + (size_t)r * (D * 2) + lc16 * 16);
            cp_async16(sbb + soff, bg + (size_t)r * (D * 2) + lc16 * 16);
        }
        CP_COMMIT();
    };

    issue(0);
    issue(1);

    // ldmatrix per-lane constants
    const int q  = lane >> 3;
    const int r8 = lane & 7;
    const uint32_t arow = (uint32_t)(((q & 1) * 8 + r8) * 128);
    const int acol = q >> 1;
    const uint32_t brow = (uint32_t)(((q >> 1) * 8 + r8) * 128);
    const int bcol = q & 1;

    float acc[4][4][4];
#pragma unroll
    for (int m = 0; m < 4; ++m)
#pragma unroll
        for (int n = 0; n < 4; ++n)
#pragma unroll
            for (int qq = 0; qq < 4; ++qq) acc[m][n][qq] = 0.f;

    const int NCH = D / BK;   // 16
    for (int c = 0; c < NCH; ++c) {
        const int st = ((unsigned)c) % STAGES;
        if (c == NCH - 1) CP_WAIT(0); else CP_WAIT(1);
        __syncthreads();
        if (c + 2 < NCH) issue(c + 2);

        const uint32_t sA = sb + st * STG_BYTES + (uint32_t)((wm * 64) * 128);
        const uint32_t sB = sb + SM_B_OFF + st * STG_BYTES + (uint32_t)((wn * 32) * 128);
#pragma unroll
        for (int ks = 0; ks < BK / 16; ++ks) {
            uint32_t a[4][4], b[4][2];
#pragma unroll
            for (int mt = 0; mt < 4; ++mt)
                ldsm_x4(a[mt], sA + (uint32_t)(mt * 16 * 128) + arow
                               + (uint32_t)((((ks * 2 + acol) ^ r8) & 7) * 16));
#pragma unroll
            for (int p = 0; p < 2; ++p) {
                uint32_t bp[4];
                ldsm_x4(bp, sB + (uint32_t)(p * 16 * 128) + brow
                            + (uint32_t)((((ks * 2 + bcol) ^ r8) & 7) * 16));
                b[2 * p][0]     = bp[0];
                b[2 * p][1]     = bp[1];
                b[2 * p + 1][0] = bp[2];
                b[2 * p + 1][1] = bp[3];
            }
#pragma unroll
            for (int mt = 0; mt < 4; ++mt)
#pragma unroll
                for (int nt = 0; nt < 4; ++nt)
                    mma_bf16(acc[mt][nt], a[mt], b[nt]);
        }
    }

    // ---- Epilogue: tile rowmax -> global atomicMax -> candidate recording ----
    __syncthreads();
    float rmax[8];
#pragma unroll
    for (int qq = 0; qq < 8; ++qq) rmax[qq] = -FLT_MAX;

#pragma unroll
    for (int mt = 0; mt < 4; ++mt) {
#pragma unroll
        for (int nt = 0; nt < 4; ++nt) {
            const int c0 = wn * 32 + nt * 8 + tig * 2;
            float s00 = n2s[c0]     - 2.f * acc[mt][nt][0];
            float s01 = n2s[c0 + 1] - 2.f * acc[mt][nt][1];
            float s10 = n2s[c0]     - 2.f * acc[mt][nt][2];
            float s11 = n2s[c0 + 1] - 2.f * acc[mt][nt][3];
            rmax[mt * 2]     = fmaxf(rmax[mt * 2],     fmaxf(s00, s01));
            rmax[mt * 2 + 1] = fmaxf(rmax[mt * 2 + 1], fmaxf(s10, s11));
        }
    }
#pragma unroll
    for (int qq = 0; qq < 8; ++qq) {
        rmax[qq] = fmaxf(rmax[qq], __shfl_xor_sync(0xFFFFFFFFu, rmax[qq], 1));
        rmax[qq] = fmaxf(rmax[qq], __shfl_xor_sync(0xFFFFFFFFu, rmax[qq], 2));
    }
    if (tig == 0) {
#pragma unroll
        for (int mt = 0; mt < 4; ++mt) {
            tmaxs[(wm * 64 + mt * 16 + g) * 4 + wn]     = rmax[mt * 2];
            tmaxs[(wm * 64 + mt * 16 + g + 8) * 4 + wn] = rmax[mt * 2 + 1];
        }
    }
    __syncthreads();
    if (tid < BM) {
        float m = fmaxf(fmaxf(tmaxs[tid * 4 + 0], tmaxs[tid * 4 + 1]),
                        fmaxf(tmaxs[tid * 4 + 2], tmaxs[tid * 4 + 3]));
        uint32_t u = enc_f(m);
        uint32_t old = atomicMax(&g_rowmaxu[i0 + tid], u);
        float cur = dec_f(old > u ? old : u);
        threshs[tid] = cur - EPS;     // <= final_rowmax - EPS: never misses argmax
    }
    __syncthreads();

#pragma unroll
    for (int mt = 0; mt < 4; ++mt) {
        const int r0 = wm * 64 + mt * 16 + g;
        const int r1 = r0 + 8;
        const float t0 = threshs[r0];
        const float t1 = threshs[r1];
#pragma unroll
        for (int nt = 0; nt < 4; ++nt) {
            const int c0 = wn * 32 + nt * 8 + tig * 2;
            float s00 = n2s[c0]     - 2.f * acc[mt][nt][0];
            float s01 = n2s[c0 + 1] - 2.f * acc[mt][nt][1];
            float s10 = n2s[c0]     - 2.f * acc[mt][nt][2];
            float s11 = n2s[c0 + 1] - 2.f * acc[mt][nt][3];
            if (s00 > t0) { int p = atomicAdd(&g_ccnt[i0 + r0], 1);
                            if (p < MAXC) g_cand[(size_t)(i0 + r0) * MAXC + p] = j0 + c0; }
            if (s01 > t0) { int p = atomicAdd(&g_ccnt[i0 + r0], 1);
                            if (p < MAXC) g_cand[(size_t)(i0 + r0) * MAXC + p] = j0 + c0 + 1; }
            if (s10 > t1) { int p = atomicAdd(&g_ccnt[i0 + r1], 1);
                            if (p < MAXC) g_cand[(size_t)(i0 + r1) * MAXC + p] = j0 + c0; }
            if (s11 > t1) { int p = atomicAdd(&g_ccnt[i0 + r1], 1);
                            if (p < MAXC) g_cand[(size_t)(i0 + r1) * MAXC + p] = j0 + c0 + 1; }
        }
    }
}

// ---------------------------------------------------------------------------
// Phase 3: warp-parallel exact fp32 rescore of the candidate list + gather.
// No scan. Candidate order is racy; (value, min-idx) merge makes the result
// order-independent and equal to jnp.argmax (first max).
// ---------------------------------------------------------------------------
__global__ void __launch_bounds__(256)
select_kernel(const float* __restrict__ A, const float* __restrict__ B,
              float* __restrict__ out) {
    const int i = blockIdx.x;
    const int tid = threadIdx.x, lane = tid & 31, wid = tid >> 5;

    __shared__ float wval[8];
    __shared__ int   widx[8];
    __shared__ int   bestj_s;

    int nc = g_ccnt[i];
    if (nc > MAXC) nc = MAXC;

    // warp-replicated A row: lane holds elems [lane*4 + k*128, +4)
    float4 areg[8];
    const float4* Arow = reinterpret_cast<const float4*>(A + (size_t)i * D);
#pragma unroll
    for (int k = 0; k < 8; ++k) areg[k] = Arow[lane + k * 32];

    float bv = -FLT_MAX;
    int   bj = 0x7fffffff;
    for (int c = wid; c < nc; c += 8) {
        const int j = g_cand[(size_t)i * MAXC + c];
        const float4* brow = reinterpret_cast<const float4*>(B + (size_t)j * D);
        float p = 0.f;
#pragma unroll
        for (int k = 0; k < 8; ++k) {
            float4 b4 = brow[lane + k * 32];
            p += areg[k].x * b4.x + areg[k].y * b4.y
               + areg[k].z * b4.z + areg[k].w * b4.w;
        }
#pragma unroll
        for (int off = 16; off > 0; off >>= 1) p += __shfl_xor_sync(0xFFFFFFFFu, p, off);
        if (lane == 0) {
            float sc = g_n2[j] - 2.f * p;
            if (sc > bv || (sc == bv && j < bj)) { bv = sc; bj = j; }
        }
    }
    if (lane == 0) { wval[wid] = bv; widx[wid] = bj; }
    __syncthreads();
    if (tid == 0) {
        float fv = -FLT_MAX; int fj = 0x7fffffff;
#pragma unroll
        for (int w = 0; w < 8; ++w) {
            float v = wval[w]; int x = widx[w];
            if (v > fv || (v == fv && x < fj)) { fv = v; fj = x; }
        }
        bestj_s = fj;
    }
    __syncthreads();

    const int j = bestj_s;
    reinterpret_cast<float4*>(out + (size_t)i * D)[tid] =
        reinterpret_cast<const float4*>(B + (size_t)j * D)[tid];
}

// ---------------------------------------------------------------------------
extern "C" void kernel_launch(void* const* d_in, const int* in_sizes, int n_in,
                              void* d_out, int out_size) {
    const float* anchor   = (const float*)d_in[0];
    const float* negative = (const float*)d_in[1];
    float* out = (float*)d_out;

    static __nv_bfloat16* s_Ah = nullptr;
    static __nv_bfloat16* s_Bh = nullptr;
    if (!s_Ah) { cudaGetSymbolAddress((void**)&s_Ah, g_Ah);
                 cudaGetSymbolAddress((void**)&s_Bh, g_Bh); }

    cudaFuncSetAttribute(gemm_kernel,
                         cudaFuncAttributeMaxDynamicSharedMemorySize, SM_TOTAL);

    cvt_all_kernel<<<2 * (N / 8), 256>>>(anchor, negative, s_Ah, s_Bh);
    gemm_kernel<<<dim3(N / BM, N / BN), 256, SM_TOTAL>>>();
    select_kernel<<<N, 256>>>(anchor, negative, out);
}